// round 1
// baseline (speedup 1.0000x reference)
#include <cuda_runtime.h>
#include <cuda_bf16.h>

// MeanAggregator: out[r, :] = mean over UNIQUE neighbors c of row r of embed[c, :]
// row_idx sorted ascending. D = 300 floats = 75 float4 per row.

#define AGG_D4   75      // 300 floats / 4
#define AGG_MAXL 2048    // staged segment cap (segments are ~Poisson(32); cap unreachable)

__global__ __launch_bounds__(128) void mean_agg_kernel(
    const int*    __restrict__ row_idx,
    const int*    __restrict__ col_idx,
    const float4* __restrict__ embed4,   // [U, 75] float4 view of [U, 300] f32
    float4*       __restrict__ out4,     // [B, 75]
    int E)
{
    const int r   = blockIdx.x;
    const int tid = threadIdx.x;

    // ---- segment [start, end) of row r via two lower_bound searches ----
    int lo = 0, hi = E;
    while (lo < hi) { int mid = (lo + hi) >> 1; if (row_idx[mid] < r)     lo = mid + 1; else hi = mid; }
    const int start = lo;
    hi = E;
    while (lo < hi) { int mid = (lo + hi) >> 1; if (row_idx[mid] < r + 1) lo = mid + 1; else hi = mid; }
    const int end = lo;
    const int L   = end - start;

    __shared__ int s_col[AGG_MAXL];
    __shared__ int s_count;
    if (tid == 0) s_count = 0;

    for (int j = tid; j < L && j < AGG_MAXL; j += blockDim.x)
        s_col[j] = col_idx[start + j];
    __syncthreads();

    // ---- dedup: later occurrences of a col within the segment -> -1 ----
    // Race note: only duplicate entries are ever overwritten with -1; the FIRST
    // occurrence of any value is never modified, so every scanning thread still
    // finds its match at (or before) the first occurrence. col values are >= 0,
    // so a concurrently-written -1 can never create a false match.
    int local = 0;
    for (int j = tid; j < L; j += blockDim.x) {
        int c = (j < AGG_MAXL) ? s_col[j] : col_idx[start + j];
        bool valid = true;
        for (int i = 0; i < j; ++i) {
            int ci = (i < AGG_MAXL) ? s_col[i] : col_idx[start + i];
            if (ci == c) { valid = false; break; }
        }
        if (valid) ++local;
        else if (j < AGG_MAXL) s_col[j] = -1;
    }
    if (local) atomicAdd(&s_count, local);
    __syncthreads();

    const int   count = s_count;
    const float inv   = 1.0f / fmaxf((float)count, 1e-8f);

    // ---- accumulate: 75 float4 lanes, deterministic segment order ----
    if (tid < AGG_D4) {
        float4 acc = make_float4(0.f, 0.f, 0.f, 0.f);
        #pragma unroll 4
        for (int j = 0; j < L; ++j) {
            int c;
            if (j < AGG_MAXL) {
                c = s_col[j];
                if (c < 0) continue;
            } else {
                // unreachable fallback: global dedup re-scan
                c = col_idx[start + j];
                bool valid = true;
                for (int i = 0; i < j; ++i)
                    if (col_idx[start + i] == c) { valid = false; break; }
                if (!valid) continue;
            }
            float4 v = embed4[(size_t)c * AGG_D4 + tid];
            acc.x += v.x; acc.y += v.y; acc.z += v.z; acc.w += v.w;
        }
        acc.x *= inv; acc.y *= inv; acc.z *= inv; acc.w *= inv;
        out4[(size_t)r * AGG_D4 + tid] = acc;
    }
}

extern "C" void kernel_launch(void* const* d_in, const int* in_sizes, int n_in,
                              void* d_out, int out_size) {
    const int*   row_idx = (const int*)  d_in[0];
    const int*   col_idx = (const int*)  d_in[1];
    const float* embed   = (const float*)d_in[2];
    float*       out     = (float*)      d_out;

    const int E = in_sizes[0];
    const int B = out_size / 300;   // D = 300

    mean_agg_kernel<<<B, 128>>>(row_idx, col_idx,
                                (const float4*)embed, (float4*)out, E);
}

// round 2
// speedup vs baseline: 1.5714x; 1.5714x over previous
#include <cuda_runtime.h>
#include <cuda_bf16.h>

// MeanAggregator: out[r,:] = mean over UNIQUE neighbors c of row r of embed[c,:]
// row_idx sorted ascending. D = 300 floats = 75 float4.

#define AGG_D4   75
#define AGG_MAXL 1024          // staged segment cap; segments avg ~32, max ~80
#define AGG_MAXB 65536         // max supported B for scratch

__device__ int g_row_start[AGG_MAXB + 1];

// Kernel 0: CSR row pointers via per-row parallel lower_bound (row_idx cached
// in L1/L2 after first touches; searches run fully in parallel across rows).
__global__ void build_row_starts(const int* __restrict__ row_idx, int E, int B) {
    int r = blockIdx.x * blockDim.x + threadIdx.x;
    if (r > B) return;
    if (r == B) { g_row_start[B] = E; return; }
    int lo = 0, hi = E;
    while (lo < hi) {
        int mid = (lo + hi) >> 1;
        if (row_idx[mid] < r) lo = mid + 1; else hi = mid;
    }
    g_row_start[r] = lo;
}

__global__ __launch_bounds__(128) void mean_agg_kernel(
    const int*    __restrict__ col_idx,
    const float4* __restrict__ embed4,   // [U, 75]
    float4*       __restrict__ out4)     // [B, 75]
{
    const int r    = blockIdx.x;
    const int tid  = threadIdx.x;
    const int lane = tid & 31;
    const int w    = tid >> 5;

    const int start = g_row_start[r];
    const int L     = g_row_start[r + 1] - start;

    __shared__ int s_col[AGG_MAXL];
    __shared__ int s_uniq[AGG_MAXL];
    __shared__ int s_wsum[4];
    __shared__ int s_base;
    if (tid == 0) s_base = 0;

    const int Lc = (L < AGG_MAXL) ? L : AGG_MAXL;
    for (int j = tid; j < Lc; j += 128) s_col[j] = col_idx[start + j];
    __syncthreads();

    // ---- dedup + ORDER-PRESERVING compaction into s_uniq (deterministic) ----
    if (L <= AGG_MAXL) {
        for (int base = 0; base < L; base += 128) {
            int  j = base + tid;
            int  c = 0;
            bool valid = false;
            if (j < L) {
                c = s_col[j];
                valid = true;
                for (int i = 0; i < j; ++i)
                    if (s_col[i] == c) { valid = false; break; }
            }
            unsigned m = __ballot_sync(0xffffffffu, valid);
            int lpfx = __popc(m & ((1u << lane) - 1u));
            if (lane == 0) s_wsum[w] = __popc(m);
            __syncthreads();
            int woff = 0;
            #pragma unroll
            for (int k = 0; k < 4; ++k) if (k < w) woff += s_wsum[k];
            if (valid) s_uniq[s_base + woff + lpfx] = c;
            __syncthreads();
            if (tid == 0) s_base += s_wsum[0] + s_wsum[1] + s_wsum[2] + s_wsum[3];
            __syncthreads();
        }
    }
    const int Lu = s_base;

    if (L <= AGG_MAXL) {
        // ---- branch-free unroll-8 gather: 8 independent LDG.128 per batch ----
        if (tid < AGG_D4) {
            const float inv = 1.0f / fmaxf((float)Lu, 1e-8f);
            float4 a0 = make_float4(0.f, 0.f, 0.f, 0.f);
            float4 a1 = make_float4(0.f, 0.f, 0.f, 0.f);
            int j = 0;
            for (; j + 8 <= Lu; j += 8) {
                int c0 = s_uniq[j+0], c1 = s_uniq[j+1], c2 = s_uniq[j+2], c3 = s_uniq[j+3];
                int c4 = s_uniq[j+4], c5 = s_uniq[j+5], c6 = s_uniq[j+6], c7 = s_uniq[j+7];
                float4 v0 = embed4[(size_t)c0 * AGG_D4 + tid];
                float4 v1 = embed4[(size_t)c1 * AGG_D4 + tid];
                float4 v2 = embed4[(size_t)c2 * AGG_D4 + tid];
                float4 v3 = embed4[(size_t)c3 * AGG_D4 + tid];
                float4 v4 = embed4[(size_t)c4 * AGG_D4 + tid];
                float4 v5 = embed4[(size_t)c5 * AGG_D4 + tid];
                float4 v6 = embed4[(size_t)c6 * AGG_D4 + tid];
                float4 v7 = embed4[(size_t)c7 * AGG_D4 + tid];
                a0.x += v0.x; a0.y += v0.y; a0.z += v0.z; a0.w += v0.w;
                a1.x += v1.x; a1.y += v1.y; a1.z += v1.z; a1.w += v1.w;
                a0.x += v2.x; a0.y += v2.y; a0.z += v2.z; a0.w += v2.w;
                a1.x += v3.x; a1.y += v3.y; a1.z += v3.z; a1.w += v3.w;
                a0.x += v4.x; a0.y += v4.y; a0.z += v4.z; a0.w += v4.w;
                a1.x += v5.x; a1.y += v5.y; a1.z += v5.z; a1.w += v5.w;
                a0.x += v6.x; a0.y += v6.y; a0.z += v6.z; a0.w += v6.w;
                a1.x += v7.x; a1.y += v7.y; a1.z += v7.z; a1.w += v7.w;
            }
            for (; j < Lu; ++j) {
                int c = s_uniq[j];
                float4 v = embed4[(size_t)c * AGG_D4 + tid];
                a0.x += v.x; a0.y += v.y; a0.z += v.z; a0.w += v.w;
            }
            float4 o;
            o.x = (a0.x + a1.x) * inv;
            o.y = (a0.y + a1.y) * inv;
            o.z = (a0.z + a1.z) * inv;
            o.w = (a0.w + a1.w) * inv;
            out4[(size_t)r * AGG_D4 + tid] = o;
        }
    } else {
        // Unreachable-for-this-data fallback: global O(L^2) dedup scan.
        __shared__ int s_cnt;
        if (tid == 0) s_cnt = 0;
        __syncthreads();
        int local = 0;
        for (int j = tid; j < L; j += 128) {
            int c = col_idx[start + j];
            bool valid = true;
            for (int i = 0; i < j; ++i)
                if (col_idx[start + i] == c) { valid = false; break; }
            if (valid) ++local;
        }
        if (local) atomicAdd(&s_cnt, local);
        __syncthreads();
        const float inv = 1.0f / fmaxf((float)s_cnt, 1e-8f);
        if (tid < AGG_D4) {
            float4 a = make_float4(0.f, 0.f, 0.f, 0.f);
            for (int j = 0; j < L; ++j) {
                int c = col_idx[start + j];
                bool valid = true;
                for (int i = 0; i < j; ++i)
                    if (col_idx[start + i] == c) { valid = false; break; }
                if (!valid) continue;
                float4 v = embed4[(size_t)c * AGG_D4 + tid];
                a.x += v.x; a.y += v.y; a.z += v.z; a.w += v.w;
            }
            a.x *= inv; a.y *= inv; a.z *= inv; a.w *= inv;
            out4[(size_t)r * AGG_D4 + tid] = a;
        }
    }
}

extern "C" void kernel_launch(void* const* d_in, const int* in_sizes, int n_in,
                              void* d_out, int out_size) {
    const int*   row_idx = (const int*)  d_in[0];
    const int*   col_idx = (const int*)  d_in[1];
    const float* embed   = (const float*)d_in[2];
    float*       out     = (float*)      d_out;

    const int E = in_sizes[0];
    const int B = out_size / 300;

    build_row_starts<<<(B + 128) / 128, 128>>>(row_idx, E, B);
    mean_agg_kernel<<<B, 128>>>(col_idx, (const float4*)embed, (float4*)out);
}

// round 3
// speedup vs baseline: 1.8780x; 1.1951x over previous
#include <cuda_runtime.h>
#include <cuda_bf16.h>

// MeanAggregator: out[r,:] = mean over UNIQUE neighbors c of row r of embed[c,:]
// row_idx sorted ascending. D = 300 floats = 75 float4. Warp-per-row design.

#define AGG_D4   75
#define AGG_MAXL 192           // per-warp staged unique cap (L ~ Poisson(32), max ~70)
#define AGG_MAXB 65536
#define WPB      8             // warps (rows) per block

__device__ int g_row_start[AGG_MAXB + 1];

// CSR row pointers by diff-scatter over the sorted row_idx (O(E), contiguous loads).
// row_start[r] = first index i with row_idx[i] >= r.
__global__ void build_row_starts(const int* __restrict__ row_idx, int E, int B) {
    int i = blockIdx.x * blockDim.x + threadIdx.x;
    if (i > E) return;
    if (i == 0) {
        int cur = row_idx[0];
        for (int v = 0; v <= cur; ++v) g_row_start[v] = 0;
    } else if (i == E) {
        int prev = row_idx[E - 1];
        for (int v = prev + 1; v <= B; ++v) g_row_start[v] = E;
    } else {
        int prev = row_idx[i - 1];
        int cur  = row_idx[i];
        for (int v = prev + 1; v <= cur; ++v) g_row_start[v] = i;
    }
}

__global__ __launch_bounds__(WPB * 32) void mean_agg_kernel(
    const int*    __restrict__ col_idx,
    const float4* __restrict__ embed4,   // [U, 75]
    float4*       __restrict__ out4,     // [B, 75]
    int B)
{
    const int w    = threadIdx.x >> 5;
    const int lane = threadIdx.x & 31;
    const int r    = blockIdx.x * WPB + w;
    if (r >= B) return;                      // warp-uniform

    const int start = g_row_start[r];
    const int L     = g_row_start[r + 1] - start;

    __shared__ int s_uniq[WPB][AGG_MAXL];
    int* su = s_uniq[w];

    float4 a0 = make_float4(0.f, 0.f, 0.f, 0.f);
    float4 a1 = a0, a2 = a0;
    const unsigned lt = (1u << lane) - 1u;
    int Lu = 0;

    if (L <= AGG_MAXL) {
        // ---- warp-synchronous order-preserving dedup ----
        for (int base = 0; base < L; base += 32) {
            int  j   = base + lane;
            bool inb = (j < L);
            // out-of-range lanes get distinct negative sentinels (never match cols >= 0)
            int  c   = inb ? col_idx[start + j] : -(lane + 1);
            unsigned peers = __match_any_sync(0xffffffffu, c);
            bool valid = inb && ((peers & lt) == 0);       // first occurrence in chunk
            if (valid) {
                for (int i = 0; i < Lu; ++i)               // vs earlier chunks' uniques
                    if (su[i] == c) { valid = false; break; }
            }
            unsigned m = __ballot_sync(0xffffffffu, valid);
            if (valid) su[Lu + __popc(m & lt)] = c;
            Lu += __popc(m);
            __syncwarp();
        }

        // ---- gather: unroll-4 over unique neighbors, 8-12 LDG.128 in flight ----
        const float4* __restrict__ e = embed4;
        int j = 0;
        for (; j + 4 <= Lu; j += 4) {
            int c0 = su[j], c1 = su[j + 1], c2 = su[j + 2], c3 = su[j + 3];
            const float4* p0 = e + (size_t)c0 * AGG_D4 + lane;
            const float4* p1 = e + (size_t)c1 * AGG_D4 + lane;
            const float4* p2 = e + (size_t)c2 * AGG_D4 + lane;
            const float4* p3 = e + (size_t)c3 * AGG_D4 + lane;
            float4 x0 = p0[0],  x1 = p1[0],  x2 = p2[0],  x3 = p3[0];
            float4 y0 = p0[32], y1 = p1[32], y2 = p2[32], y3 = p3[32];
            if (lane < AGG_D4 - 64) {
                float4 z0 = p0[64], z1 = p1[64], z2 = p2[64], z3 = p3[64];
                a2.x += z0.x + z1.x + z2.x + z3.x;
                a2.y += z0.y + z1.y + z2.y + z3.y;
                a2.z += z0.z + z1.z + z2.z + z3.z;
                a2.w += z0.w + z1.w + z2.w + z3.w;
            }
            a0.x += x0.x + x1.x + x2.x + x3.x;
            a0.y += x0.y + x1.y + x2.y + x3.y;
            a0.z += x0.z + x1.z + x2.z + x3.z;
            a0.w += x0.w + x1.w + x2.w + x3.w;
            a1.x += y0.x + y1.x + y2.x + y3.x;
            a1.y += y0.y + y1.y + y2.y + y3.y;
            a1.z += y0.z + y1.z + y2.z + y3.z;
            a1.w += y0.w + y1.w + y2.w + y3.w;
        }
        for (; j < Lu; ++j) {
            const float4* p = e + (size_t)su[j] * AGG_D4 + lane;
            float4 x = p[0], y = p[32];
            if (lane < AGG_D4 - 64) {
                float4 z = p[64];
                a2.x += z.x; a2.y += z.y; a2.z += z.z; a2.w += z.w;
            }
            a0.x += x.x; a0.y += x.y; a0.z += x.z; a0.w += x.w;
            a1.x += y.x; a1.y += y.y; a1.z += y.z; a1.w += y.w;
        }
    } else {
        // Unreachable-for-this-data fallback: O(L^2) global dedup, direct accumulate.
        for (int j = 0; j < L; ++j) {
            int c = col_idx[start + j];
            bool valid = true;
            for (int i = 0; i < j; ++i)
                if (col_idx[start + i] == c) { valid = false; break; }
            if (!valid) continue;
            ++Lu;
            const float4* p = embed4 + (size_t)c * AGG_D4 + lane;
            float4 x = p[0], y = p[32];
            if (lane < AGG_D4 - 64) {
                float4 z = p[64];
                a2.x += z.x; a2.y += z.y; a2.z += z.z; a2.w += z.w;
            }
            a0.x += x.x; a0.y += x.y; a0.z += x.z; a0.w += x.w;
            a1.x += y.x; a1.y += y.y; a1.z += y.z; a1.w += y.w;
        }
    }

    const float inv = 1.0f / fmaxf((float)Lu, 1e-8f);
    float4* o = out4 + (size_t)r * AGG_D4 + lane;
    float4 t;
    t.x = a0.x * inv; t.y = a0.y * inv; t.z = a0.z * inv; t.w = a0.w * inv;
    o[0] = t;
    t.x = a1.x * inv; t.y = a1.y * inv; t.z = a1.z * inv; t.w = a1.w * inv;
    o[32] = t;
    if (lane < AGG_D4 - 64) {
        t.x = a2.x * inv; t.y = a2.y * inv; t.z = a2.z * inv; t.w = a2.w * inv;
        o[64] = t;
    }
}

extern "C" void kernel_launch(void* const* d_in, const int* in_sizes, int n_in,
                              void* d_out, int out_size) {
    const int*   row_idx = (const int*)  d_in[0];
    const int*   col_idx = (const int*)  d_in[1];
    const float* embed   = (const float*)d_in[2];
    float*       out     = (float*)      d_out;

    const int E = in_sizes[0];
    const int B = out_size / 300;

    build_row_starts<<<(E + 1 + 255) / 256, 256>>>(row_idx, E, B);
    mean_agg_kernel<<<(B + WPB - 1) / WPB, WPB * 32>>>(
        col_idx, (const float4*)embed, (float4*)out, B);
}